// round 2
// baseline (speedup 1.0000x reference)
#include <cuda_runtime.h>
#include <cuda_bf16.h>

// Problem constants
#define B_   4
#define N_   262144          // elements per batch (2^18)
#define F_   64
#define S_   1024            // NUM_SEG
#define OUT_ 64
#define CAP  512             // bin capacity (Poisson lambda=256, >15 sigma headroom)

// ---------------- device scratch (no allocations allowed) ----------------
// Zero block (one memsetAsync per call):
//   [0, 4096)       cnt_row  int [B][S]
//   [4096, 8192)    cnt_col  int [B][S]
//   [8192, 8448)    gsum     float [B][64]
__device__ __align__(256) unsigned g_zeroblk[2 * B_ * S_ + B_ * 64];
#define CNT_ROW ((int*)g_zeroblk)
#define CNT_COL (((int*)g_zeroblk) + B_ * S_)
#define GSUM    ((float*)(g_zeroblk + 2 * B_ * S_))

__device__ __align__(256) int g_bins[2 * B_ * S_ * CAP];   // 16 MB: [side][B][S][CAP] elem ids

__device__ __align__(256) float g_M[4 * F_ * OUT_];     // M_self, M_row, M_col, M_glob
__device__ __align__(256) float g_bias_const[OUT_];
__device__ __align__(256) float g_rowvec[B_ * S_ * OUT_];
__device__ __align__(256) float g_colvec[B_ * S_ * OUT_];
__device__ __align__(256) float g_biasb[B_ * OUT_];

// ---------------- packed fp32x2 helpers (sm_103a FFMA2) ----------------
__device__ __forceinline__ unsigned long long pk2(float x) {
    unsigned long long r;
    asm("mov.b64 %0, {%1, %1};" : "=l"(r) : "f"(x));
    return r;
}
__device__ __forceinline__ void fma2(unsigned long long& d, unsigned long long a, unsigned long long b) {
    asm("fma.rn.f32x2 %0, %1, %2, %0;" : "+l"(d) : "l"(a), "l"(b));
}
__device__ __forceinline__ float2 up2(unsigned long long v) {
    float2 r;
    asm("mov.b64 {%0, %1}, %2;" : "=f"(r.x), "=f"(r.y) : "l"(v));
    return r;
}

// ---------------- K0: fold weight matrices ----------------
__global__ void prep_kernel(const float* __restrict__ Wself, const float* __restrict__ Wrow,
                            const float* __restrict__ Wcol,  const float* __restrict__ Wglob,
                            const float* __restrict__ Wout,
                            const float* __restrict__ bself, const float* __restrict__ brow,
                            const float* __restrict__ bcol,  const float* __restrict__ bglob,
                            const float* __restrict__ bout) {
    const int stride = blockDim.x * gridDim.x;
    const int tid = blockIdx.x * blockDim.x + threadIdx.x;
    for (int job = tid; job < 4 * F_ * OUT_; job += stride) {
        const int m = job >> 12;
        const int r = job & 4095;
        const int f = r >> 6, o = r & 63;
        const float* W = (m == 0) ? Wself : (m == 1) ? Wrow : (m == 2) ? Wcol : Wglob;
        float acc = 0.f;
        #pragma unroll 16
        for (int j = 0; j < 64; ++j)
            acc += W[f * 64 + j] * Wout[(m * 64 + j) * OUT_ + o];
        g_M[job] = acc;
    }
    for (int o = tid; o < OUT_; o += stride) {
        float acc = bout[o];
        for (int j = 0; j < 64; ++j) {
            acc += bself[j] * Wout[j * OUT_ + o];
            acc += brow [j] * Wout[(64  + j) * OUT_ + o];
            acc += bcol [j] * Wout[(128 + j) * OUT_ + o];
            acc += bglob[j] * Wout[(192 + j) * OUT_ + o];
        }
        g_bias_const[o] = acc;
    }
}

// ---------------- K1: binning (replaces float atomic scatter) ----------------
// One thread per element: claim slot via int atomicAdd, store element id.
__global__ void __launch_bounds__(256) bin_kernel(const int* __restrict__ index) {
    const int e = blockIdx.x * 256 + threadIdx.x;     // 0 .. B*N-1
    const int b = e >> 18;
    const int local = e & (N_ - 1);
    const int2 p = ((const int2*)index)[e];
    const int r = (b << 10) + p.x;
    const int c = (b << 10) + p.y;
    int pos0 = atomicAdd(CNT_ROW + r, 1);
    if (pos0 < CAP) g_bins[r * CAP + pos0] = local;
    int pos1 = atomicAdd(CNT_COL + c, 1);
    if (pos1 < CAP) g_bins[(B_ * S_ + c) * CAP + pos1] = local;
}

// ---------------- K2: per-segment reduce + fused GEMV ----------------
// One warp per (side, b, seg) job. Gather value rows from the bin, sum in regs,
// compute mean, then rowvec/colvec = mean @ M_{row,col} via shuffle-broadcast.
// Row-side warps also push their sum into GSUM (for the global-mean path).
__global__ void __launch_bounds__(256) reduce_kernel(const float* __restrict__ value) {
    __shared__ float Ms[2 * 4096];   // M_row then M_col
    const int tid = threadIdx.x;
    { // stage both fold matrices
        const float4* src = (const float4*)(g_M + 4096);
        float4* dst = (float4*)Ms;
        #pragma unroll
        for (int i = 0; i < 8; ++i) dst[tid + i * 256] = src[tid + i * 256];
    }
    __syncthreads();

    const int warp = tid >> 5, lane = tid & 31;
    const int job = blockIdx.x * 8 + warp;            // 0 .. 8191
    const int side = job >> 12;                        // 0=row 1=col
    const int bs = job & 4095;                         // b*1024 + s
    const int b = bs >> 10;

    const int cnt = (side ? CNT_COL : CNT_ROW)[bs];
    const int mn = min(cnt, CAP);
    const int* ids = g_bins + ((long long)side * B_ * S_ + bs) * CAP;
    const float* vb = value + ((long long)b << 24);    // batch base (N*64 floats)

    float2 acc = make_float2(0.f, 0.f);
    for (int base = 0; base < mn; base += 32) {
        const int idx_l = min(base + lane, mn - 1);
        const int idv = ids[idx_l];
        const int m = min(32, mn - base);
        #pragma unroll 4
        for (int j = 0; j < m; ++j) {
            const int id = __shfl_sync(0xffffffff, idv, j);
            const float2 v = *(const float2*)(vb + ((long long)id << 6) + (lane << 1));
            acc.x += v.x;
            acc.y += v.y;
        }
    }

    if (side == 0) {   // feed global-sum path (every element appears exactly once per side)
        atomicAdd(GSUM + b * 64 + (lane << 1),     acc.x);
        atomicAdd(GSUM + b * 64 + (lane << 1) + 1, acc.y);
    }

    const float inv = 1.0f / ((float)cnt + 1e-9f);
    const float2 mean = make_float2(acc.x * inv, acc.y * inv);   // f = 2*lane, 2*lane+1

    // GEMV: out[o] = sum_f mean[f] * M[f][o]; lane computes o=lane and o=lane+32
    const float* M = Ms + side * 4096;
    float r0 = 0.f, r1 = 0.f;
    #pragma unroll 8
    for (int j = 0; j < 32; ++j) {
        const float m0 = __shfl_sync(0xffffffff, mean.x, j);   // f = 2j
        const float m1 = __shfl_sync(0xffffffff, mean.y, j);   // f = 2j+1
        r0 += m0 * M[(2 * j) * 64 + lane]      + m1 * M[(2 * j + 1) * 64 + lane];
        r1 += m0 * M[(2 * j) * 64 + lane + 32] + m1 * M[(2 * j + 1) * 64 + lane + 32];
    }
    float* dst = (side ? g_colvec : g_rowvec) + ((long long)bs << 6);
    dst[lane]      = r0;
    dst[lane + 32] = r1;
}

// ---------------- K3: per-batch bias (global mean path) ----------------
__global__ void gbias_kernel() {
    __shared__ float gmean[64];
    const int b = blockIdx.x, t = threadIdx.x;
    gmean[t] = GSUM[b * 64 + t] * (1.0f / (float)N_);
    __syncthreads();
    float bias = g_bias_const[t];
    #pragma unroll
    for (int f = 0; f < 64; ++f) bias += gmean[f] * g_M[3 * 4096 + f * 64 + t];
    g_biasb[b * 64 + t] = bias;
}

// ---------------- K4: fused GEMV + gather + LReLU ----------------
#define SMEM_MAIN ((128*68 + 4096)*4 + 256*4)
__global__ void __launch_bounds__(256) main_kernel(const float* __restrict__ value,
                                                   const int* __restrict__ index,
                                                   float* __restrict__ out) {
    extern __shared__ float sm[];
    float* Vs = sm;                 // [128][68] padded value tile
    float* Ms = sm + 128 * 68;      // [64][64] M_self
    int*   Is = (int*)(Ms + 4096);  // [128][2]
    const int tid = threadIdx.x;
    const long long base = (long long)blockIdx.x * 128;
    const int b = (int)(base >> 18);

    {
        const float4* Mg = (const float4*)g_M;
        float4* Md = (float4*)Ms;
        #pragma unroll
        for (int i = 0; i < 4; ++i) Md[tid + i * 256] = Mg[tid + i * 256];
    }
    {
        const float4* Vg = (const float4*)(value + (base << 6));
        #pragma unroll
        for (int i = 0; i < 8; ++i) {
            const int li = tid + i * 256;
            const float4 v = Vg[li];
            const int L = li << 2;
            const int r = L >> 6, c = L & 63;
            *(float4*)(Vs + r * 68 + c) = v;
        }
    }
    if (tid < 128) {
        const int2 p = ((const int2*)index)[base + tid];
        Is[2 * tid] = p.x; Is[2 * tid + 1] = p.y;
    }
    __syncthreads();

    const int tx = tid & 7, ty = tid >> 3;
    const int o0 = tx << 3;
    const int r0 = ty << 2;

    unsigned long long acc[4][4];
    #pragma unroll
    for (int j = 0; j < 4; ++j)
        #pragma unroll
        for (int p = 0; p < 4; ++p) acc[j][p] = 0ull;

    #pragma unroll 8
    for (int k = 0; k < 64; ++k) {
        const ulonglong2 mA = *(const ulonglong2*)(Ms + k * 64 + o0);
        const ulonglong2 mB = *(const ulonglong2*)(Ms + k * 64 + o0 + 4);
        #pragma unroll
        for (int j = 0; j < 4; ++j) {
            const unsigned long long a = pk2(Vs[(r0 + j) * 68 + k]);
            fma2(acc[j][0], a, mA.x);
            fma2(acc[j][1], a, mA.y);
            fma2(acc[j][2], a, mB.x);
            fma2(acc[j][3], a, mB.y);
        }
    }

    const float4 bb0 = *(const float4*)(g_biasb + b * 64 + o0);
    const float4 bb1 = *(const float4*)(g_biasb + b * 64 + o0 + 4);
    #pragma unroll
    for (int j = 0; j < 4; ++j) {
        const int r = r0 + j;
        const int i0 = Is[2 * r], i1 = Is[2 * r + 1];
        const float* rv = g_rowvec + ((((long long)b << 10) + i0) << 6) + o0;
        const float* cv = g_colvec + ((((long long)b << 10) + i1) << 6) + o0;
        const float4 R0 = *(const float4*)rv,       R1 = *(const float4*)(rv + 4);
        const float4 C0 = *(const float4*)cv,       C1 = *(const float4*)(cv + 4);
        const float2 a0 = up2(acc[j][0]), a1 = up2(acc[j][1]);
        const float2 a2 = up2(acc[j][2]), a3 = up2(acc[j][3]);
        float o_[8] = { a0.x + R0.x + C0.x + bb0.x,
                        a0.y + R0.y + C0.y + bb0.y,
                        a1.x + R0.z + C0.z + bb0.z,
                        a1.y + R0.w + C0.w + bb0.w,
                        a2.x + R1.x + C1.x + bb1.x,
                        a2.y + R1.y + C1.y + bb1.y,
                        a3.x + R1.z + C1.z + bb1.z,
                        a3.y + R1.w + C1.w + bb1.w };
        #pragma unroll
        for (int q = 0; q < 8; ++q) o_[q] = fmaxf(o_[q], 0.01f * o_[q]);
        float* op = out + ((base + r) << 6) + o0;
        *(float4*)op       = make_float4(o_[0], o_[1], o_[2], o_[3]);
        *(float4*)(op + 4) = make_float4(o_[4], o_[5], o_[6], o_[7]);
    }
}

// ---------------- index pass-through ----------------
__global__ void idxcopy_kernel(const int* __restrict__ idx, float* __restrict__ out, int n4) {
    const int i = blockIdx.x * blockDim.x + threadIdx.x;
    if (i < n4) {
        const int4 v = ((const int4*)idx)[i];
        ((float4*)out)[i] = make_float4((float)v.x, (float)v.y, (float)v.z, (float)v.w);
    }
}

// ---------------- launch ----------------
extern "C" void kernel_launch(void* const* d_in, const int* in_sizes, int n_in,
                              void* d_out, int out_size) {
    const int*   index = (const int*)d_in[0];
    const float* value = (const float*)d_in[1];
    const float* Wself = (const float*)d_in[2];
    const float* bself = (const float*)d_in[3];
    const float* Wrow  = (const float*)d_in[4];
    const float* brow  = (const float*)d_in[5];
    const float* Wcol  = (const float*)d_in[6];
    const float* bcol  = (const float*)d_in[7];
    const float* Wglob = (const float*)d_in[8];
    const float* bglob = (const float*)d_in[9];
    const float* Wout  = (const float*)d_in[10];
    const float* bout  = (const float*)d_in[11];
    float* out = (float*)d_out;

    const long long main_elems = (long long)B_ * N_ * OUT_;
    const long long off = (long long)out_size - main_elems;
    float* out_main = (off > 0) ? (out + off) : out;

    void* zp = nullptr;
    cudaGetSymbolAddress(&zp, g_zeroblk);
    cudaMemsetAsync(zp, 0, sizeof(g_zeroblk), 0);

    cudaFuncSetAttribute(main_kernel, cudaFuncAttributeMaxDynamicSharedMemorySize, SMEM_MAIN);

    prep_kernel<<<64, 256>>>(Wself, Wrow, Wcol, Wglob, Wout, bself, brow, bcol, bglob, bout);
    bin_kernel<<<(B_ * N_) / 256, 256>>>(index);
    reduce_kernel<<<1024, 256>>>(value);
    gbias_kernel<<<B_, 64>>>();
    main_kernel<<<(B_ * N_) / 128, 256, SMEM_MAIN>>>(value, index, out_main);

    if (off > 0) {
        const int n4 = (int)(off / 4);
        idxcopy_kernel<<<(n4 + 255) / 256, 256>>>(index, out, n4);
    }
}